// round 2
// baseline (speedup 1.0000x reference)
#include <cuda_runtime.h>
#include <cstdint>

#define B_  8
#define S_  2048
#define N_  4096
#define D_  256
#define MAX_W_ 16

// One span per 32-thread warp-half... actually one span per 32 threads (a full warp
// covers exactly one span -> all predicates warp-uniform, zero divergence).
// Each thread owns 8 consecutive floats of D=256 (two float4 loads).
// blockDim = 256 -> 8 spans per block, grid = 4096.
__global__ __launch_bounds__(256) void pooling_span_kernel(
    const float4* __restrict__ seq4,    // [B, S, D/4]
    const int2*   __restrict__ spans,   // [B, N]
    float4*       __restrict__ out4)    // [B, N, D/4]
{
    const int span = blockIdx.x * 8 + (threadIdx.x >> 5);   // 0 .. B*N-1
    const int lane = threadIdx.x & 31;                      // owns float4 slots 2*lane, 2*lane+1
    const int b = span >> 12;                               // N_ = 4096 = 2^12

    const int2 se   = spans[span];
    const int start = se.x;
    const int end   = se.y;
    // mask(w) = (w <= width) && (end - w >= 0)  ==  w <= min(width, end)
    const int m = min(end - start, end);

    // Address of this thread's slice of row `end`; each unrolled iteration is a
    // compile-time immediate offset below it (LDG [R + imm]).
    const float4* __restrict__ p = seq4
        + (size_t)b * (S_ * (D_ / 4))
        + (size_t)end * (D_ / 4)
        + 2 * lane;

    float4 a0 = make_float4(0.f, 0.f, 0.f, 0.f);
    float4 a1 = make_float4(0.f, 0.f, 0.f, 0.f);

#pragma unroll
    for (int w = 0; w < MAX_W_; ++w) {
        if (w <= m) {                         // warp-uniform predicate
            const float4 v0 = __ldg(p - w * (D_ / 4));
            const float4 v1 = __ldg(p - w * (D_ / 4) + 1);
            a0.x += v0.x; a0.y += v0.y; a0.z += v0.z; a0.w += v0.w;
            a1.x += v1.x; a1.y += v1.y; a1.z += v1.z; a1.w += v1.w;
        }
    }

    // count = #w with mask true = m+1 (clamped below by TINY, matching reference)
    const float inv = 1.0f / fmaxf((float)(m + 1), 1e-13f);
    a0.x *= inv; a0.y *= inv; a0.z *= inv; a0.w *= inv;
    a1.x *= inv; a1.y *= inv; a1.z *= inv; a1.w *= inv;

    float4* __restrict__ o = out4 + (size_t)span * (D_ / 4) + 2 * lane;
    o[0] = a0;
    o[1] = a1;
}

extern "C" void kernel_launch(void* const* d_in, const int* in_sizes, int n_in,
                              void* d_out, int out_size)
{
    const float4* seq4  = (const float4*)d_in[0];  // sequence_tensor [B,S,D] f32
    const int2*   spans = (const int2*)  d_in[1];  // span_indices    [B,N,2] i32
    float4*       out4  = (float4*)d_out;          // [B,N,D] f32

    const int total_spans = B_ * N_;               // 32768
    const int blocks = total_spans / 8;            // 4096 blocks of 256 threads
    pooling_span_kernel<<<blocks, 256>>>(seq4, spans, out4);
}

// round 3
// speedup vs baseline: 1.4332x; 1.4332x over previous
#include <cuda_runtime.h>
#include <cstdint>

#define B_  8
#define S_  2048
#define N_  4096
#define D_  256
#define MAX_W_ 16

// One span per warp (predicates warp-uniform, zero divergence).
// Each thread owns float4 slot `lane` and slot `lane+32` -> each LDG.128 is
// warp-contiguous over 512B (4 x 128B lines), minimizing L1 wavefronts.
// blockDim = 256 -> 8 spans per block, grid = 4096.
__global__ __launch_bounds__(256) void pooling_span_kernel(
    const float4* __restrict__ seq4,    // [B, S, D/4]
    const int2*   __restrict__ spans,   // [B, N]
    float4*       __restrict__ out4)    // [B, N, D/4]
{
    const int span = blockIdx.x * 8 + (threadIdx.x >> 5);   // 0 .. B*N-1
    const int lane = threadIdx.x & 31;
    const int b = span >> 12;                               // N_ = 4096 = 2^12

    const int2 se   = spans[span];
    const int start = se.x;
    const int end   = se.y;
    // mask(w) = (w <= width) && (end - w >= 0)  ==  w <= min(width, end)
    const int m = min(end - start, end);

    // This thread's slice of row `end`; every unrolled iteration addresses
    // base - w*256B and base - w*256B + 512B as compile-time immediates.
    const float4* __restrict__ p = seq4
        + (size_t)b * (S_ * (D_ / 4))
        + (size_t)end * (D_ / 4)
        + lane;

    float4 a0 = make_float4(0.f, 0.f, 0.f, 0.f);
    float4 a1 = make_float4(0.f, 0.f, 0.f, 0.f);

#pragma unroll
    for (int w = 0; w < MAX_W_; ++w) {
        if (w <= m) {                         // warp-uniform predicate
            const float4 v0 = __ldg(p - w * (D_ / 4));        // slots  lane   (bytes 0..511)
            const float4 v1 = __ldg(p - w * (D_ / 4) + 32);   // slots lane+32 (bytes 512..1023)
            a0.x += v0.x; a0.y += v0.y; a0.z += v0.z; a0.w += v0.w;
            a1.x += v1.x; a1.y += v1.y; a1.z += v1.z; a1.w += v1.w;
        }
    }

    // count = m+1 (clamped below by TINY, matching reference)
    const float inv = 1.0f / fmaxf((float)(m + 1), 1e-13f);
    a0.x *= inv; a0.y *= inv; a0.z *= inv; a0.w *= inv;
    a1.x *= inv; a1.y *= inv; a1.z *= inv; a1.w *= inv;

    float4* __restrict__ o = out4 + (size_t)span * (D_ / 4) + lane;
    o[0]  = a0;
    o[32] = a1;
}

extern "C" void kernel_launch(void* const* d_in, const int* in_sizes, int n_in,
                              void* d_out, int out_size)
{
    const float4* seq4  = (const float4*)d_in[0];  // sequence_tensor [B,S,D] f32
    const int2*   spans = (const int2*)  d_in[1];  // span_indices    [B,N,2] i32
    float4*       out4  = (float4*)d_out;          // [B,N,D] f32

    const int total_spans = B_ * N_;               // 32768
    const int blocks = total_spans / 8;            // 4096 blocks of 256 threads
    pooling_span_kernel<<<blocks, 256>>>(seq4, spans, out4);
}